// round 11
// baseline (speedup 1.0000x reference)
#include <cuda_runtime.h>
#include <cstdint>

#define B_    64
#define S_    2048
#define H_    1024
#define SPLIT 16
#define CHUNK (S_ / SPLIT)      // 128 timesteps per CTA
#define GROUPS 2                // independent 128-thread warpgroups per CTA
#define GROWS (CHUNK / GROUPS)  // 64 rows per group
#define TILE  4
#define NTILES (GROWS / TILE)   // 16
#define THREADS 256
#define GW 4                    // warps per group
#define NSLOT (SPLIT * GROUPS)  // 32 partial slots per batch

// Scratch (allocation-free: __device__ globals)
__device__ float g_expE [B_ * S_];              // exp(tanh(score)) per (b,s)
__device__ float g_partL[B_ * NSLOT];           // partial sum of exp per slot
__device__ float g_partC[B_ * NSLOT * H_];      // partial context (8 MiB)
__device__ int   g_count[B_];                   // arrival counter per batch

// ---------------------------------------------------------------------------
// Fused kernel: single DRAM read of rnn_output.
// CTA = 2 INDEPENDENT warpgroups (warps 0-3 / 4-7); groups never sync with
// each other -> 8 independent phases per SM, load bursts decorrelate.
// Within a group: thread owns float4 columns {tg, tg+128}. Per tile of 4 rows:
//   front-batched loads (8 float4, MLP=8) -> per-row partial dot -> warp
//   reduce -> lane0 publishes to ping-pong red -> bar.sync(1+g,128) ->
//   lanes 0-3 of each warp redundantly finish (4-way sum + exp(tanh(.)))
//   -> shuffle broadcast -> acc += t*xr (registers).
// tanh in [-1,1] -> softmax needs no max subtraction.
// Epilogue: threadfence-reduction; last CTA per batch reduces 32 partials,
// writes context + weights. Counter reset by finisher (graph-replayable).
// ---------------------------------------------------------------------------
__global__ __launch_bounds__(THREADS, 4)
void fused_kernel(const float* __restrict__ x,
                  const float* __restrict__ w,
                  const float* __restrict__ bptr,
                  float* __restrict__ ctx_out,
                  float* __restrict__ wts_out)
{
    __shared__ float red[GROUPS][2][GW * TILE];  // per-group ping-pong partials
    __shared__ int   s_last;
    __shared__ float s_inv;

    const int tid  = threadIdx.x;
    const int warp = tid >> 5;
    const int lane = tid & 31;
    const int g    = warp >> 2;          // group 0/1
    const int wg   = warp & 3;           // warp within group
    const int tg   = tid & 127;          // thread within group
    const float bias = __ldg(bptr);

    const int b     = blockIdx.x / SPLIT;
    const int chunk = blockIdx.x % SPLIT;
    const int s0    = chunk * CHUNK + g * GROWS;

    // per-thread weight slice: float4 columns tg and tg+128
    const float4 w0 = reinterpret_cast<const float4*>(w)[tg];
    const float4 w1 = reinterpret_cast<const float4*>(w)[tg + 128];

    float4 acc0 = make_float4(0.f, 0.f, 0.f, 0.f);
    float4 acc1 = make_float4(0.f, 0.f, 0.f, 0.f);
    float lsum = 0.f;                    // group warp 0, lanes 0-3

    const float4* X = reinterpret_cast<const float4*>(x) +
                      ((size_t)b * S_ + s0) * (H_ / 4);

    #pragma unroll 1
    for (int tile = 0; tile < NTILES; tile++) {
        const int p = tile & 1;
        const float4* xp = X + (size_t)tile * TILE * (H_ / 4);

        // front-batched loads: 4 rows x 2 float4 (MLP=8)
        float4 xr0[TILE], xr1[TILE];
        #pragma unroll
        for (int s = 0; s < TILE; s++) {
            xr0[s] = xp[(size_t)s * (H_ / 4) + tg];
            xr1[s] = xp[(size_t)s * (H_ / 4) + tg + 128];
        }

        // per-row partial dots
        float d[TILE];
        #pragma unroll
        for (int s = 0; s < TILE; s++)
            d[s] = xr0[s].x * w0.x + xr0[s].y * w0.y
                 + xr0[s].z * w0.z + xr0[s].w * w0.w
                 + xr1[s].x * w1.x + xr1[s].y * w1.y
                 + xr1[s].z * w1.z + xr1[s].w * w1.w;

        // warp reduce (lane 0 holds result)
        #pragma unroll
        for (int s = 0; s < TILE; s++) {
            #pragma unroll
            for (int off = 16; off; off >>= 1)
                d[s] += __shfl_xor_sync(0xffffffffu, d[s], off);
        }
        if (lane == 0) {
            #pragma unroll
            for (int s = 0; s < TILE; s++)
                red[g][p][wg * TILE + s] = d[s];
        }

        // group-scoped named barrier (128 threads; ping-pong -> one per tile)
        asm volatile("bar.sync %0, %1;" :: "r"(1 + g), "r"(128) : "memory");

        // redundant finish: lanes 0-3 of each warp own one row each
        float t = 0.f;
        if (lane < TILE) {
            float v = red[g][p][0 * TILE + lane]
                    + red[g][p][1 * TILE + lane]
                    + red[g][p][2 * TILE + lane]
                    + red[g][p][3 * TILE + lane];
            t = __expf(tanhf(v + bias));
            if (wg == 0) {
                g_expE[(size_t)b * S_ + s0 + tile * TILE + lane] = t;
                lsum += t;
            }
        }

        // broadcast t and accumulate from registers
        #pragma unroll
        for (int s = 0; s < TILE; s++) {
            const float ts = __shfl_sync(0xffffffffu, t, s);
            acc0.x += ts * xr0[s].x; acc0.y += ts * xr0[s].y;
            acc0.z += ts * xr0[s].z; acc0.w += ts * xr0[s].w;
            acc1.x += ts * xr1[s].x; acc1.y += ts * xr1[s].y;
            acc1.z += ts * xr1[s].z; acc1.w += ts * xr1[s].w;
        }
    }

    // flush this group's partial context + lsum (slot per (chunk, group))
    const int slot = (b * SPLIT + chunk) * GROUPS + g;
    {
        float4* pc = reinterpret_cast<float4*>(g_partC + (size_t)slot * H_);
        pc[tg]       = acc0;
        pc[tg + 128] = acc1;
    }
    if (wg == 0) {
        // lanes 0-3 hold partial lsums (others are 0): sum within lanes 0-3
        lsum += __shfl_xor_sync(0xffffffffu, lsum, 1);
        lsum += __shfl_xor_sync(0xffffffffu, lsum, 2);
        if (lane == 0) g_partL[slot] = lsum;
    }

    // -------- finisher election (threadfence reduction pattern) --------
    __syncthreads();                 // both groups' flushes issued
    __threadfence();
    if (tid == 0) {
        const int old = atomicAdd(&g_count[b], 1);
        s_last = (old == SPLIT - 1);
        if (s_last) g_count[b] = 0;  // reset for next replay (all arrived)
    }
    __syncthreads();
    if (!s_last) return;
    __threadfence();                 // acquire: see peers' flushes

    // -------- epilogue: this CTA finishes batch b --------
    if (tid < 32) {
        float l = 0.f;
        #pragma unroll
        for (int c = 0; c < NSLOT; c += 32)
            l += g_partL[b * NSLOT + c + tid];
        #pragma unroll
        for (int off = 16; off; off >>= 1)
            l += __shfl_xor_sync(0xffffffffu, l, off);
        if (tid == 0) s_inv = 1.f / l;
    }
    __syncthreads();
    const float inv = s_inv;

    // context[b][:] : 256 threads x one float4, 32 independent partial loads
    float4 c4 = make_float4(0.f, 0.f, 0.f, 0.f);
    #pragma unroll
    for (int cc = 0; cc < NSLOT; cc++) {
        float4 v = reinterpret_cast<const float4*>(
            g_partC + ((size_t)b * NSLOT + cc) * H_)[tid];
        c4.x += v.x; c4.y += v.y; c4.z += v.z; c4.w += v.w;
    }
    c4.x *= inv; c4.y *= inv; c4.z *= inv; c4.w *= inv;
    reinterpret_cast<float4*>(ctx_out)[b * (H_ / 4) + tid] = c4;

    // weights[b][:] : S/4 = 512 float4, 2 per thread
    #pragma unroll
    for (int i = 0; i < S_ / 4 / THREADS; i++) {
        const int idx = b * (S_ / 4) + i * THREADS + tid;
        float4 e = reinterpret_cast<const float4*>(g_expE)[idx];
        e.x *= inv; e.y *= inv; e.z *= inv; e.w *= inv;
        reinterpret_cast<float4*>(wts_out)[idx] = e;
    }
}

extern "C" void kernel_launch(void* const* d_in, const int* in_sizes, int n_in,
                              void* d_out, int out_size)
{
    const float* x    = (const float*)d_in[0];   // rnn_output [B,S,H]
    const float* w    = (const float*)d_in[1];   // attn_w [H]
    const float* bptr = (const float*)d_in[2];   // attn_b scalar

    float* out = (float*)d_out;                  // context [B,H] then weights [B,S]
    float* ctx_out = out;
    float* wts_out = out + (size_t)B_ * H_;

    fused_kernel<<<B_ * SPLIT, THREADS>>>(x, w, bptr, ctx_out, wts_out);
}

// round 12
// speedup vs baseline: 1.0073x; 1.0073x over previous
#include <cuda_runtime.h>
#include <cstdint>

#define B_    64
#define S_    2048
#define H_    1024
#define SPLIT 16
#define CHUNK (S_ / SPLIT)      // 128 timesteps per CTA
#define TILE  4
#define NTILES (CHUNK / TILE)   // 32
#define THREADS 256             // one float4 column slice per thread
#define WARPS (THREADS / 32)

// Scratch (allocation-free: __device__ globals)
__device__ float g_expE [B_ * S_];             // exp(tanh(score)) per (b,s)
__device__ float g_partL[B_ * SPLIT];          // partial sum of exp per chunk
__device__ float g_partC[B_ * SPLIT * H_];     // partial context per chunk (4 MiB)
__device__ int   g_count[B_];                  // arrival counter per batch

// ---------------------------------------------------------------------------
// Fused kernel, software-pipelined (R10 base + cache-policy hints):
//  - x loads use __ldcs (evict-first streaming: x is single-use, consumed
//    from registers twice within the tile, never re-read from memory)
//  - partC/partL/expE scratch uses __stcg/__ldcg (L2-only; producer CTA !=
//    consumer CTA so L1 allocation is pure overhead)
//  - outputs via __stcs (never re-read)
// Thread t owns H columns [4t,4t+4). TILE=4 with register double-buffering:
// tile k+1's loads issue BEFORE tile k's reduce/barrier, keeping DRAM busy
// through the barrier bubble. tanh in [-1,1] -> softmax needs no max.
// Epilogue: threadfence-reduction; 16th CTA per batch finishes context +
// weights (deterministic, graph-replayable; counter reset by finisher).
// ---------------------------------------------------------------------------
__global__ __launch_bounds__(THREADS, 4)
void fused_kernel(const float* __restrict__ x,
                  const float* __restrict__ w,
                  const float* __restrict__ bptr,
                  float* __restrict__ ctx_out,
                  float* __restrict__ wts_out)
{
    __shared__ float red[2][WARPS * TILE];   // ping-pong per-warp dot partials
    __shared__ float lred[TILE];
    __shared__ int   s_last;
    __shared__ float s_inv;

    const int b     = blockIdx.x / SPLIT;
    const int chunk = blockIdx.x % SPLIT;
    const int tid   = threadIdx.x;
    const int warp  = tid >> 5;
    const int lane  = tid & 31;
    const float bias = __ldg(bptr);
    const float4 w4 = reinterpret_cast<const float4*>(w)[tid];

    float4 acc = make_float4(0.f, 0.f, 0.f, 0.f);
    float lsum = 0.f;                        // warp 0, lanes 0-3 accumulate

    const int s0 = chunk * CHUNK;
    const float4* xp0 = reinterpret_cast<const float4*>(x) +
                        ((size_t)b * S_ + s0) * (H_ / 4) + tid;

    float4 xa[TILE], xb[TILE];

    // preload tile 0 into xa (streaming)
    #pragma unroll
    for (int s = 0; s < TILE; s++)
        xa[s] = __ldcs(&xp0[(size_t)s * (H_ / 4)]);

    // one pipelined tile step: consume cur[], prefetch tile nt into nxt[]
    auto step = [&](int tile, float4* cur, float4* nxt) {
        const int p = tile & 1;

        // prefetch next tile (clamped: last tile re-loads itself, in-bounds)
        const int nt = (tile + 1 < NTILES) ? tile + 1 : NTILES - 1;
        const float4* xpn = xp0 + (size_t)nt * TILE * (H_ / 4);
        #pragma unroll
        for (int s = 0; s < TILE; s++)
            nxt[s] = __ldcs(&xpn[(size_t)s * (H_ / 4)]);

        // dots from current buffer
        float d[TILE];
        #pragma unroll
        for (int s = 0; s < TILE; s++)
            d[s] = cur[s].x * w4.x + cur[s].y * w4.y
                 + cur[s].z * w4.z + cur[s].w * w4.w;

        // full warp reduce (lane 0 holds result)
        #pragma unroll
        for (int s = 0; s < TILE; s++) {
            #pragma unroll
            for (int off = 16; off; off >>= 1)
                d[s] += __shfl_xor_sync(0xffffffffu, d[s], off);
        }

        if (lane == 0) {
            #pragma unroll
            for (int s = 0; s < TILE; s++)
                red[p][warp * TILE + s] = d[s];
        }
        __syncthreads();                      // single barrier per tile

        // redundant finish in every warp: lanes 0-3 own one timestep each
        float t = 0.f;
        if (lane < TILE) {
            float v = 0.f;
            #pragma unroll
            for (int j = 0; j < WARPS; j++)
                v += red[p][j * TILE + lane];
            t = __expf(tanhf(v + bias));
            if (warp == 0) {
                __stcg(&g_expE[(size_t)b * S_ + s0 + tile * TILE + lane], t);
                lsum += t;
            }
        }

        // broadcast t and accumulate from the current register buffer
        #pragma unroll
        for (int s = 0; s < TILE; s++) {
            const float ts = __shfl_sync(0xffffffffu, t, s);
            acc.x += ts * cur[s].x;
            acc.y += ts * cur[s].y;
            acc.z += ts * cur[s].z;
            acc.w += ts * cur[s].w;
        }
    };

    #pragma unroll 1
    for (int t2 = 0; t2 < NTILES; t2 += 2) {
        step(t2,     xa, xb);
        step(t2 + 1, xb, xa);
    }

    // flush partial context (L2-only: consumer is a different CTA)
    __stcg(&reinterpret_cast<float4*>(
               g_partC + ((size_t)b * SPLIT + chunk) * H_)[tid], acc);

    // combine warp-0 lane lsums -> partL
    if (warp == 0 && lane < TILE) lred[lane] = lsum;
    __syncthreads();
    if (tid == 0) {
        float l = 0.f;
        #pragma unroll
        for (int i = 0; i < TILE; i++) l += lred[i];
        __stcg(&g_partL[b * SPLIT + chunk], l);
    }

    // -------- finisher election (threadfence reduction pattern) --------
    __threadfence();
    __syncthreads();
    if (tid == 0) {
        const int old = atomicAdd(&g_count[b], 1);
        s_last = (old == SPLIT - 1);
        if (s_last) g_count[b] = 0;   // reset for next replay (all arrived)
    }
    __syncthreads();
    if (!s_last) return;
    __threadfence();                  // acquire: see peers' flushes

    // -------- epilogue: this CTA finishes batch b --------
    if (tid < 32) {
        float l = (tid < SPLIT) ? __ldcg(&g_partL[b * SPLIT + tid]) : 0.f;
        #pragma unroll
        for (int off = 16; off; off >>= 1)
            l += __shfl_xor_sync(0xffffffffu, l, off);
        if (tid == 0) s_inv = 1.f / l;
    }
    __syncthreads();
    const float inv = s_inv;

    // context[b][:] : 256 threads x one float4, 16 independent partial loads
    float4 c = make_float4(0.f, 0.f, 0.f, 0.f);
    #pragma unroll
    for (int cc = 0; cc < SPLIT; cc++) {
        float4 v = __ldcg(&reinterpret_cast<const float4*>(
            g_partC + ((size_t)b * SPLIT + cc) * H_)[tid]);
        c.x += v.x; c.y += v.y; c.z += v.z; c.w += v.w;
    }
    c.x *= inv; c.y *= inv; c.z *= inv; c.w *= inv;
    __stcs(&reinterpret_cast<float4*>(ctx_out)[b * (H_ / 4) + tid], c);

    // weights[b][:] : S/4 = 512 float4, 2 per thread
    #pragma unroll
    for (int i = 0; i < S_ / 4 / THREADS; i++) {
        const int idx = b * (S_ / 4) + i * THREADS + tid;
        float4 e = __ldcg(&reinterpret_cast<const float4*>(g_expE)[idx]);
        e.x *= inv; e.y *= inv; e.z *= inv; e.w *= inv;
        __stcs(&reinterpret_cast<float4*>(wts_out)[idx], e);
    }
}

extern "C" void kernel_launch(void* const* d_in, const int* in_sizes, int n_in,
                              void* d_out, int out_size)
{
    const float* x    = (const float*)d_in[0];   // rnn_output [B,S,H]
    const float* w    = (const float*)d_in[1];   // attn_w [H]
    const float* bptr = (const float*)d_in[2];   // attn_b scalar

    float* out = (float*)d_out;                  // context [B,H] then weights [B,S]
    float* ctx_out = out;
    float* wts_out = out + (size_t)B_ * H_;

    fused_kernel<<<B_ * SPLIT, THREADS>>>(x, w, bptr, ctx_out, wts_out);
}